// round 17
// baseline (speedup 1.0000x reference)
#include <cuda_runtime.h>
#include <math.h>

// LSEP loss: out = log1p( sum_rows (sum_{t==0} e^x) * (sum_{t>0} e^{-x}) )
// input: [32768, 1000] fp32, target: [32768, 1000] int32 (values in {0,1}),
// out: [1] fp32.
//
// R13: R11 structure (persistent single-wave grid, lean ex2.approx math,
// front-batched 4x LDG.128 per pair-step, __ldcs streaming, one RED.F64 per
// block, ticket finalize), with occupancy raised 4 -> 6 CTAs/SM
// (__launch_bounds__(256,6) => <=42 regs) and the persistent grid scaled to
// 888 = 148 x 6 (still one wave). R12's software pipeline is reverted: it
// measured neutral (44.0 -> 44.2 us), proving per-warp latency was already
// hidden; the remaining lever is chip-wide outstanding-load count via more
// resident warps.

#define ROWS 32768
#define COLS 1000
#define VEC4_PER_ROW (COLS / 4)   // 250
#define WARPS_PER_BLOCK 8
#define THREADS (WARPS_PER_BLOCK * 32)
#define ROW_GROUPS (ROWS / WARPS_PER_BLOCK)   // 4096
#define GRID_P (148 * 6)                      // 888 CTAs -> one wave at occ 6

#define LOG2E 1.4426950408889634f

__device__ double g_total;          // static-init 0; reset to 0 by last block
__device__ unsigned int g_done;     // static-init 0; reset to 0 by last block

// 6 instrs/element: ISETP (shared by SEL + pred), FSEL, FMUL, MUFU.EX2,
// FADD (S), predicated FADD (P). exp(+-x) == ex2(x * +-log2e).
__device__ __forceinline__ void proc4(float4 x, int4 t, float& S, float& P)
{
    float c0 = (t.x != 0) ? -LOG2E : LOG2E;
    float c1 = (t.y != 0) ? -LOG2E : LOG2E;
    float c2 = (t.z != 0) ? -LOG2E : LOG2E;
    float c3 = (t.w != 0) ? -LOG2E : LOG2E;

    float e0, e1, e2, e3;
    asm("ex2.approx.ftz.f32 %0, %1;" : "=f"(e0) : "f"(x.x * c0));
    asm("ex2.approx.ftz.f32 %0, %1;" : "=f"(e1) : "f"(x.y * c1));
    asm("ex2.approx.ftz.f32 %0, %1;" : "=f"(e2) : "f"(x.z * c2));
    asm("ex2.approx.ftz.f32 %0, %1;" : "=f"(e3) : "f"(x.w * c3));

    S += (e0 + e1) + (e2 + e3);
    if (t.x != 0) P += e0;
    if (t.y != 0) P += e1;
    if (t.z != 0) P += e2;
    if (t.w != 0) P += e3;
}

__global__ __launch_bounds__(THREADS, 6) void lsep_kernel(
    const float* __restrict__ input,
    const int* __restrict__ target,
    float* __restrict__ out)
{
    const int warp = threadIdx.x >> 5;
    const int lane = threadIdx.x & 31;

    double acc = 0.0;   // per-warp sum over processed rows of sneg*spos (lane0 meaningful)

    for (int iter = blockIdx.x; iter < ROW_GROUPS; iter += GRID_P) {
        const int row = iter * WARPS_PER_BLOCK + warp;

        const float4* in4 = reinterpret_cast<const float4*>(input) + (size_t)row * VEC4_PER_ROW;
        const int4*   tg4 = reinterpret_cast<const int4*>(target)  + (size_t)row * VEC4_PER_ROW;

        float S = 0.0f;   // sum of all exps (both classes)
        float P = 0.0f;   // sum_{t==1} exp(-x)

        // 250 vec4s per row, lanes stride 32: j = lane + k*32, k = 0..7.
        // k = 0..6 valid for all lanes; k = 7 only for lane < 26.
        // Pairs of chunks: 4 LDG.128 front-batched per step (2 KB/warp in flight).
        #pragma unroll
        for (int k = 0; k < 3; k++) {
            int j0 = lane + k * 64;
            int j1 = j0 + 32;
            float4 x0 = __ldcs(&in4[j0]);
            int4   t0 = __ldcs(&tg4[j0]);
            float4 x1 = __ldcs(&in4[j1]);
            int4   t1 = __ldcs(&tg4[j1]);
            proc4(x0, t0, S, P);
            proc4(x1, t1, S, P);
        }
        {
            int j0 = lane + 192;           // always valid
            int j1 = j0 + 32;              // valid iff lane < 26
            float4 x0 = __ldcs(&in4[j0]);
            int4   t0 = __ldcs(&tg4[j0]);
            if (j1 < VEC4_PER_ROW) {
                float4 x1 = __ldcs(&in4[j1]);
                int4   t1 = __ldcs(&tg4[j1]);
                proc4(x0, t0, S, P);
                proc4(x1, t1, S, P);
            } else {
                proc4(x0, t0, S, P);
            }
        }

        // warp reduction of both partials
        #pragma unroll
        for (int off = 16; off > 0; off >>= 1) {
            S += __shfl_xor_sync(0xFFFFFFFFu, S, off);
            P += __shfl_xor_sync(0xFFFFFFFFu, P, off);
        }

        if (lane == 0) {
            float sneg = S - P;   // sum_{t==0} exp(x)
            acc += (double)sneg * (double)P;
        }
    }

    // block reduction of per-warp accumulators (once per kernel)
    __shared__ double s_prod[WARPS_PER_BLOCK];
    if (lane == 0) s_prod[warp] = acc;
    __syncthreads();

    if (warp == 0) {
        double v = (lane < WARPS_PER_BLOCK) ? s_prod[lane] : 0.0;
        #pragma unroll
        for (int off = 4; off > 0; off >>= 1) {
            v += __shfl_xor_sync(0xFFFFFFFFu, v, off);
        }
        if (lane == 0) {
            atomicAdd(&g_total, v);          // no return use -> RED.F64 (L2-side)
            __threadfence();
            unsigned int ticket = atomicAdd(&g_done, 1u);
            if (ticket == (unsigned int)(GRID_P - 1)) {
                // Read through the L2 atomic path so we observe the
                // authoritative atomic accumulator, not a stale cached line.
                double total = atomicAdd(&g_total, 0.0);
                out[0] = (float)log1p(total);
                g_total = 0.0;               // reset for next graph replay
                g_done  = 0u;
            }
        }
    }
}

extern "C" void kernel_launch(void* const* d_in, const int* in_sizes, int n_in,
                              void* d_out, int out_size) {
    const float* input  = (const float*)d_in[0];
    const int*   target = (const int*)d_in[1];
    float*       out    = (float*)d_out;

    lsep_kernel<<<GRID_P, THREADS>>>(input, target, out);
}